// round 9
// baseline (speedup 1.0000x reference)
#include <cuda_runtime.h>
#include <cuda_bf16.h>
#include <cstdint>

// Embedding gather: out[t, :] = W_E[tokens[t], :]
// tokens: int32 [32768], W_E: float32 [50257, 768], out: float32 [32768, 768]
//
// R8 -> R9: all concurrency/cache mechanisms converge at ~125MB @ 4.6-4.9 TB/s;
// concurrency and L2 policy are NOT the limiter. Last untested lever: request
// granularity. sm_103a supports 256-bit global accesses (v8.b32) - and the
// immediate .L2::evict_last form is legal exactly at that width (per R7 ptxas
// error). Halve memory-op count: each thread moves 32B per row.
// CTA = 192 threads, 16 rows: thread t owns bytes [(t%96)*32, +32) of rows
// t0 + 2s + (t/96), s = 0..7. 8x LDG.256 (evict_last) batched, 8x STG.256 (cs).

#define D_MODEL   768
#define ROW_BYTES 3072
#define TPR       96        // threads per row (32B each)
#define U         8         // row-pairs per CTA -> 16 rows
#define ROWS_PER_CTA (2 * U)

__global__ __launch_bounds__(192) void embed_gather_v8_kernel(
    const int* __restrict__ tokens,
    const unsigned char* __restrict__ W,
    unsigned char* __restrict__ out,
    int n_tok)
{
    const int t    = threadIdx.x;
    const int half = t / TPR;             // 0 or 1
    const int boff = (t % TPR) * 32;      // byte offset within a row
    const int t0   = blockIdx.x * ROWS_PER_CTA;

    if (t0 + ROWS_PER_CTA <= n_tok) {
        int rows[U];
#pragma unroll
        for (int s = 0; s < U; ++s)
            rows[s] = __ldg(tokens + t0 + 2 * s + half);

        uint32_t v[U][8];
#pragma unroll
        for (int s = 0; s < U; ++s) {
            const unsigned char* src = W + (size_t)rows[s] * ROW_BYTES + boff;
            asm volatile(
                "ld.global.nc.L2::evict_last.v8.b32 "
                "{%0, %1, %2, %3, %4, %5, %6, %7}, [%8];"
                : "=r"(v[s][0]), "=r"(v[s][1]), "=r"(v[s][2]), "=r"(v[s][3]),
                  "=r"(v[s][4]), "=r"(v[s][5]), "=r"(v[s][6]), "=r"(v[s][7])
                : "l"(src));
        }

#pragma unroll
        for (int s = 0; s < U; ++s) {
            unsigned char* dst =
                out + (size_t)(t0 + 2 * s + half) * ROW_BYTES + boff;
            asm volatile(
                "st.global.cs.v8.b32 [%0], "
                "{%1, %2, %3, %4, %5, %6, %7, %8};"
                :: "l"(dst),
                   "r"(v[s][0]), "r"(v[s][1]), "r"(v[s][2]), "r"(v[s][3]),
                   "r"(v[s][4]), "r"(v[s][5]), "r"(v[s][6]), "r"(v[s][7])
                : "memory");
        }
    } else {
        // tail: plain 32B-per-thread copy, one row at a time
        for (int r = t0 + half; r < n_tok; r += 2) {
            const int row = __ldg(tokens + r);
            uint32_t w[8];
            const unsigned char* src = W + (size_t)row * ROW_BYTES + boff;
            asm volatile(
                "ld.global.nc.v8.b32 {%0, %1, %2, %3, %4, %5, %6, %7}, [%8];"
                : "=r"(w[0]), "=r"(w[1]), "=r"(w[2]), "=r"(w[3]),
                  "=r"(w[4]), "=r"(w[5]), "=r"(w[6]), "=r"(w[7])
                : "l"(src));
            unsigned char* dst = out + (size_t)r * ROW_BYTES + boff;
            asm volatile(
                "st.global.cs.v8.b32 [%0], {%1, %2, %3, %4, %5, %6, %7, %8};"
                :: "l"(dst),
                   "r"(w[0]), "r"(w[1]), "r"(w[2]), "r"(w[3]),
                   "r"(w[4]), "r"(w[5]), "r"(w[6]), "r"(w[7])
                : "memory");
        }
    }
}

extern "C" void kernel_launch(void* const* d_in, const int* in_sizes, int n_in,
                              void* d_out, int out_size)
{
    const int* tokens      = (const int*)d_in[0];
    const unsigned char* W = (const unsigned char*)d_in[1];
    unsigned char* out     = (unsigned char*)d_out;

    const int n_tok = in_sizes[0];   // 32768
    const int grid  = (n_tok + ROWS_PER_CTA - 1) / ROWS_PER_CTA;  // 2048

    embed_gather_v8_kernel<<<grid, 192>>>(tokens, W, out, n_tok);
}